// round 15
// baseline (speedup 1.0000x reference)
#include <cuda_runtime.h>
#include <mma.h>
#include <math.h>
#include <stdint.h>

using namespace nvcuda;

// Problem constants
#define Bn   512
#define Rr   5
#define Nn   64
#define Ff   172
#define Tt   100
#define Ee   272     // F + T
#define Kk   444     // F + EF + T
#define Dhh  136     // E / H
#define OUTF 172
#define CATN 1532    // R*E + F
#define QRT  16      // neighbor rows per attention CTA
#define F1SPLIT 12
#define F1CHUNK 128
#define F2SPLIT 4
#define F2CHUNK 44

// ---------------- inter-kernel scratch ----------------
__device__ __align__(256) float g_X[Bn * Ee];
__device__ __align__(256) float g_q[Bn * Rr * Ee];
__device__ __align__(256) float g_qk[Bn * Rr * 2 * Kk];
__device__ __align__(256) float g_ctx[Bn * Rr * 2 * Kk];
__device__ __align__(256) float g_attn[Bn * Rr * Ee];
__device__ __align__(256) float g_cat[Bn * CATN];
__device__ __align__(256) float g_h1[Bn * OUTF];
__device__ __align__(256) float g_inv[Bn * Rr];
__device__ int g_mask_u8;
// attention partials
__device__ __align__(256) float g_pctx[Bn * Rr * 4 * 2 * Kk];
__device__ __align__(256) float g_pml [Bn * Rr * 4 * 4];
__device__ __align__(256) float g_pw  [Bn * Rr * 4 * 2 * QRT];
// split-K partials
__device__ __align__(256) float g_f1p[F1SPLIT * Bn * OUTF];
__device__ __align__(256) float g_f2p[F2SPLIT * Bn * OUTF];

__device__ __forceinline__ float warp_reduce(float v) {
    #pragma unroll
    for (int o = 16; o; o >>= 1) v += __shfl_down_sync(0xffffffffu, v, o);
    return v;
}
__device__ __forceinline__ float dot4(float4 a, float4 b) {
    return a.x * b.x + a.y * b.y + a.z * b.z + a.w * b.w;
}

// ==================== prep (+ mask dtype detect in extra block) ====================
__global__ __launch_bounds__(256)
void prep_X_kernel(const float* __restrict__ src_node,
                   const float* __restrict__ src_time,
                   const unsigned int* __restrict__ mask_words)
{
    const int b = blockIdx.x, tid = threadIdx.x;
    if (b == Bn) {
        const int nwords = 8192;
        unsigned int acc = 0;
        for (int i = tid; i < nwords; i += 256) acc |= mask_words[i];
        __shared__ unsigned int red[8];
        unsigned int v = acc;
        #pragma unroll
        for (int o = 16; o; o >>= 1) v |= __shfl_xor_sync(0xffffffffu, v, o);
        if ((tid & 31) == 0) red[tid >> 5] = v;
        __syncthreads();
        if (tid == 0) {
            unsigned int t = 0;
            #pragma unroll
            for (int w = 0; w < 8; ++w) t |= red[w];
            g_mask_u8 = (t > 1u) ? 1 : 0;
        }
        return;
    }
    for (int e = tid; e < Ee; e += 256)
        g_X[b * Ee + e] = (e < Ff) ? src_node[b * Ff + e]
                                   : src_time[b * Tt + (e - Ff)];
    for (int j = tid; j < Ff; j += 256)
        g_cat[b * CATN + Rr * Ee + j] = src_node[b * Ff + j];
}

// ==================== tf32 tensor-core GEMM: 64x64 tile, 3-pass compensation ====
// Same interface/semantics as the fp32 gemm2: C = A @ B(k,n) (+epilogue).
// BT=true: B row-major [N,K] (NT); BT=false: B row-major [K,N] (NN)
// epi: 0=bias, 1=bias+relu, 2=bias+zero-if-invalid, 3=raw partial (splitK)
// K / kChunk multiples of 4 (float4 K-loads); M multiple of 64.
#define TLD 72   // smem row stride (floats): 288B, 32B-aligned rows
template<bool BT>
__global__ __launch_bounds__(128, 4)
void gemm_tc_kernel(const float* __restrict__ A, int lda, long strideAz,
                    const float* __restrict__ B, int ldb, long strideBz,
                    float* __restrict__ C, int ldc, long strideCz,
                    const float* __restrict__ bias, long strideBiasZ,
                    const float* __restrict__ invf, int invRowStride,
                    int N, int K, int epi, int kChunk)
{
    // flat buffer: Ahi | Alo | Bhi | Blo (each 16 x TLD); reused as Cs (64 x TLD)
    __shared__ __align__(32) float sbuf[4 * 16 * TLD];
    float* Ahi = sbuf;
    float* Alo = sbuf + 16 * TLD;
    float* Bhi = sbuf + 32 * TLD;
    float* Blo = sbuf + 48 * TLD;

    const int z = blockIdx.z;
    int Keff = K;
    if (kChunk > 0) {
        const int ko = z * kChunk;
        Keff = min(kChunk, K - ko);
        A += ko;
        B += BT ? (long)ko : (long)ko * ldb;
    } else {
        A += (size_t)z * strideAz;
        B += (size_t)z * strideBz;
    }
    C += (size_t)z * strideCz;
    const float* bz = bias ? bias + (size_t)z * strideBiasZ : nullptr;
    const int m0 = blockIdx.x * 64, n0 = blockIdx.y * 64;
    const int tid = threadIdx.x;
    const int warp = tid >> 5;
    const int m0w = (warp >> 1) * 32;     // warp row offset in tile
    const int n0w = (warp & 1) * 32;      // warp col offset in tile

    wmma::fragment<wmma::accumulator, 16, 16, 8, float> acc[2][2];
    #pragma unroll
    for (int i = 0; i < 2; ++i)
        #pragma unroll
        for (int j = 0; j < 2; ++j) wmma::fill_fragment(acc[i][j], 0.f);

    for (int k0 = 0; k0 < Keff; k0 += 16) {
        // ---- A tile fill: Ahi/Alo[k][m] ----
        {
            const int c = tid & 3, mbase = tid >> 2;
            #pragma unroll
            for (int i = 0; i < 2; ++i) {
                const int mm = mbase + 32 * i;
                const int k = k0 + 4 * c;
                float4 v = make_float4(0.f, 0.f, 0.f, 0.f);
                if (k < Keff) v = *(const float4*)&A[(size_t)(m0 + mm) * lda + k];
                const float f[4] = {v.x, v.y, v.z, v.w};
                #pragma unroll
                for (int q = 0; q < 4; ++q) {
                    const float h = wmma::__float_to_tf32(f[q]);
                    const float l = wmma::__float_to_tf32(f[q] - h);
                    Ahi[(4 * c + q) * TLD + mm] = h;
                    Alo[(4 * c + q) * TLD + mm] = l;
                }
            }
        }
        // ---- B tile fill: Bhi/Blo[k][n] ----
        if (BT) {
            const int c = tid & 3, nbase = tid >> 2;
            #pragma unroll
            for (int i = 0; i < 2; ++i) {
                const int nn = nbase + 32 * i;
                const int k = k0 + 4 * c;
                float4 v = make_float4(0.f, 0.f, 0.f, 0.f);
                if (k < Keff && (n0 + nn) < N)
                    v = *(const float4*)&B[(size_t)(n0 + nn) * ldb + k];
                const float f[4] = {v.x, v.y, v.z, v.w};
                #pragma unroll
                for (int q = 0; q < 4; ++q) {
                    const float h = wmma::__float_to_tf32(f[q]);
                    const float l = wmma::__float_to_tf32(f[q] - h);
                    Bhi[(4 * c + q) * TLD + nn] = h;
                    Blo[(4 * c + q) * TLD + nn] = l;
                }
            }
        } else {
            const int n4 = (tid & 15) * 4, kb = tid >> 4;
            #pragma unroll
            for (int i = 0; i < 2; ++i) {
                const int k = kb + 8 * i;
                float4 v = make_float4(0.f, 0.f, 0.f, 0.f);
                if ((k0 + k) < Keff && (n0 + n4) < N)
                    v = *(const float4*)&B[(size_t)(k0 + k) * ldb + n0 + n4];
                const float f[4] = {v.x, v.y, v.z, v.w};
                #pragma unroll
                for (int q = 0; q < 4; ++q) {
                    const float h = wmma::__float_to_tf32(f[q]);
                    const float l = wmma::__float_to_tf32(f[q] - h);
                    Bhi[k * TLD + n4 + q] = h;
                    Blo[k * TLD + n4 + q] = l;
                }
            }
        }
        __syncthreads();

        // ---- tensor-core compute: 2 k8 steps ----
        #pragma unroll
        for (int kk = 0; kk < 16; kk += 8) {
            wmma::fragment<wmma::matrix_a, 16, 16, 8, wmma::precision::tf32, wmma::col_major> ah[2], al[2];
            wmma::fragment<wmma::matrix_b, 16, 16, 8, wmma::precision::tf32, wmma::row_major> bh[2], bl[2];
            #pragma unroll
            for (int t = 0; t < 2; ++t) {
                wmma::load_matrix_sync(ah[t], &Ahi[kk * TLD + m0w + 16 * t], TLD);
                wmma::load_matrix_sync(al[t], &Alo[kk * TLD + m0w + 16 * t], TLD);
                wmma::load_matrix_sync(bh[t], &Bhi[kk * TLD + n0w + 16 * t], TLD);
                wmma::load_matrix_sync(bl[t], &Blo[kk * TLD + n0w + 16 * t], TLD);
            }
            #pragma unroll
            for (int i = 0; i < 2; ++i)
                #pragma unroll
                for (int j = 0; j < 2; ++j) {
                    wmma::mma_sync(acc[i][j], ah[i], bh[j], acc[i][j]);
                    wmma::mma_sync(acc[i][j], al[i], bh[j], acc[i][j]);
                    wmma::mma_sync(acc[i][j], ah[i], bl[j], acc[i][j]);
                }
        }
        __syncthreads();
    }

    // ---- store accumulators to smem (reuse sbuf as Cs[64][TLD]) ----
    float* Cs = sbuf;
    #pragma unroll
    for (int i = 0; i < 2; ++i)
        #pragma unroll
        for (int j = 0; j < 2; ++j)
            wmma::store_matrix_sync(&Cs[(m0w + 16 * i) * TLD + n0w + 16 * j],
                                    acc[i][j], TLD, wmma::mem_row_major);
    __syncthreads();

    // ---- epilogue ----
    for (int t = tid; t < 64 * 64; t += 128) {
        const int rr = t >> 6, cc = t & 63;
        const int row = m0 + rr, col = n0 + cc;
        if (col < N) {
            float v = Cs[rr * TLD + cc];
            if (epi != 3 && bz) v += bz[col];
            if (epi == 1) v = fmaxf(v, 0.f);
            if (epi == 2 && invf) {
                const float fl = invf[z + (size_t)row * invRowStride];
                if (fl > 0.5f) v = 0.f;
            }
            C[(size_t)row * ldc + col] = v;
        }
    }
}

// ==================== splitK reduce ====================
__global__ void reduce_kernel(const float* __restrict__ P, int nsplit, int total,
                              int ncol, const float* __restrict__ bias, int relu,
                              float* __restrict__ out)
{
    const int i = blockIdx.x * 256 + threadIdx.x;
    if (i < total) {
        float s = bias[i % ncol];
        for (int z = 0; z < nsplit; ++z) s += P[(size_t)z * total + i];
        if (relu) s = fmaxf(s, 0.f);
        out[i] = s;
    }
}

// ==================== attention: 4-way split (R10), float4 smem traffic ====================
#define AK_LD  448                  // row stride (floats); 112 float4
#define NSEG_F 43
#define NSEG_T 25
#define AF4_A  (QRT * NSEG_F)                       // 688
#define AF4_TOT (QRT * (2 * NSEG_F + NSEG_T))       // 1776

__global__ __launch_bounds__(128, 7)
void attn_q_kernel(const float* __restrict__ neigh_feat,
                   const float* __restrict__ neigh_time,
                   const float* __restrict__ edge_feat,
                   const void* __restrict__ mask_raw)
{
    __shared__ float kin[QRT * AK_LD];     // 28672 B
    __shared__ float ssm[2][QRT];
    __shared__ float ws[2][QRT];
    __shared__ float msk[QRT];

    const int b = blockIdx.x, r = blockIdx.y, qrt = blockIdx.z;
    const int idx = b * Rr + r;
    const int n0 = qrt * QRT;
    const int tid = threadIdx.x;
    const int lane = tid & 31, warp = tid >> 5;
    const float4 zero4 = make_float4(0.f, 0.f, 0.f, 0.f);

    if (tid < QRT) {
        const int mi = (r * Bn + b) * Nn + n0 + tid;
        int mv;
        if (g_mask_u8) mv = ((const unsigned char*)mask_raw)[mi];
        else           mv = ((const int*)mask_raw)[mi];
        msk[tid] = (mv != 0) ? 1.f : 0.f;
    }
    if (tid < QRT * 4)
        kin[(tid >> 2) * AK_LD + Kk + (tid & 3)] = 0.f;

    // load kin quarter-tile: 1776 independent float4
    {
        const float4* pa = (const float4*)(neigh_feat + ((size_t)idx * Nn + n0) * Ff);
        const float4* pb = (const float4*)(edge_feat  + ((size_t)idx * Nn + n0) * Ff);
        const float4* pc = (const float4*)(neigh_time + ((size_t)idx * Nn + n0) * Tt);
        #pragma unroll
        for (int it = 0; it < 14; ++it) {
            const int t = tid + it * 128;
            if (t < AF4_TOT) {
                float4 v;
                int row, col;
                if (t < AF4_A) {
                    row = t / NSEG_F; const int s = t - row * NSEG_F;
                    col = s * 4; v = pa[row * NSEG_F + s];
                } else if (t < 2 * AF4_A) {
                    const int t2 = t - AF4_A;
                    row = t2 / NSEG_F; const int s = t2 - row * NSEG_F;
                    col = Ff + s * 4; v = pb[row * NSEG_F + s];
                } else {
                    const int t2 = t - 2 * AF4_A;
                    row = t2 / NSEG_T; const int s = t2 - row * NSEG_T;
                    col = 2 * Ff + s * 4; v = pc[row * NSEG_T + s];
                }
                *(float4*)&kin[row * AK_LD + col] = v;
            }
        }
    }

    // qk coefficients: float4 registers straight from gmem (L2-hot)
    float4 q0[4], q1[4];
    {
        const float4* qkg4 = (const float4*)&g_qk[(size_t)idx * (2 * Kk)];
        #pragma unroll
        for (int k = 0; k < 4; ++k) {
            const int c = lane + 32 * k;
            const bool ok = (c < 111);
            q0[k] = ok ? qkg4[c]       : zero4;
            q1[k] = ok ? qkg4[111 + c] : zero4;
        }
    }
    __syncthreads();

    // scores: warp w -> rows w*4 .. w*4+3 (LDS.128)
    {
        const float scale = rsqrtf((float)Dhh);
        #pragma unroll
        for (int i = 0; i < 4; ++i) {
            const int nl = warp * 4 + i;
            const float4* krow = (const float4*)&kin[nl * AK_LD];
            float a0 = 0.f, a1 = 0.f;
            #pragma unroll
            for (int k = 0; k < 3; ++k) {
                const float4 v = krow[lane + 32 * k];
                a0 += dot4(v, q0[k]);
                a1 += dot4(v, q1[k]);
            }
            if (lane < 15) {
                const float4 v = krow[lane + 96];
                a0 += dot4(v, q0[3]);
                a1 += dot4(v, q1[3]);
            }
            a0 = warp_reduce(a0);
            a1 = warp_reduce(a1);
            if (lane == 0) {
                const bool pad = msk[nl] > 0.5f;
                ssm[0][nl] = pad ? -1e30f : a0 * scale;
                ssm[1][nl] = pad ? -1e30f : a1 * scale;
            }
        }
    }
    __syncthreads();

    // local flash stats (warp 0; lanes 0..15 -> h0, 16..31 -> h1)
    if (warp == 0) {
        const int h = lane >> 4, p = lane & 15;
        float s = ssm[h][p];
        float m = s;
        #pragma unroll
        for (int o = 8; o; o >>= 1) m = fmaxf(m, __shfl_xor_sync(0xffffffffu, m, o));
        const float e = (msk[p] > 0.5f) ? 0.f : __expf(s - m);
        float l = e;
        #pragma unroll
        for (int o = 8; o; o >>= 1) l += __shfl_xor_sync(0xffffffffu, l, o);
        ws[h][p] = e;
        g_pw[((size_t)idx * 4 + qrt) * 32 + h * 16 + p] = e;
        if (p == 0) {
            g_pml[((size_t)idx * 4 + qrt) * 4 + h * 2 + 0] = m;
            g_pml[((size_t)idx * 4 + qrt) * 4 + h * 2 + 1] = l;
        }
    }
    __syncthreads();

    // partial ctx: one float4 column per thread (LDS.128)
    if (tid < 111) {
        float* pout = &g_pctx[((size_t)idx * 4 + qrt) * (2 * Kk)];
        float4 acc0 = zero4, acc1 = zero4;
        #pragma unroll
        for (int n = 0; n < QRT; ++n) {
            const float4 v = *(const float4*)&kin[n * AK_LD + 4 * tid];
            const float w0 = ws[0][n], w1 = ws[1][n];
            acc0.x += w0 * v.x; acc0.y += w0 * v.y;
            acc0.z += w0 * v.z; acc0.w += w0 * v.w;
            acc1.x += w1 * v.x; acc1.y += w1 * v.y;
            acc1.z += w1 * v.z; acc1.w += w1 * v.w;
        }
        *(float4*)&pout[4 * tid]      = acc0;
        *(float4*)&pout[Kk + 4 * tid] = acc1;
    }
}

// ==================== merge 4 quarters (float4) ====================
__global__ __launch_bounds__(128)
void merge4_kernel(float* __restrict__ wavg_out)
{
    const int idx = blockIdx.x;
    const int tid = threadIdx.x;
    __shared__ float fs[4][2];
    __shared__ int inval;

    if (tid == 0) {
        bool bad = false;
        #pragma unroll
        for (int h = 0; h < 2; ++h) {
            float m[4], l[4];
            float M = -1e38f;
            #pragma unroll
            for (int s = 0; s < 4; ++s) {
                m[s] = g_pml[((size_t)idx * 4 + s) * 4 + h * 2 + 0];
                l[s] = g_pml[((size_t)idx * 4 + s) * 4 + h * 2 + 1];
                M = fmaxf(M, m[s]);
            }
            float L = 0.f, e[4];
            #pragma unroll
            for (int s = 0; s < 4; ++s) { e[s] = __expf(m[s] - M); L += l[s] * e[s]; }
            if (L <= 0.f) { bad = true; fs[0][h] = fs[1][h] = fs[2][h] = fs[3][h] = 0.f; }
            else {
                const float inv = 1.f / L;
                #pragma unroll
                for (int s = 0; s < 4; ++s) fs[s][h] = e[s] * inv;
            }
        }
        inval = bad ? 1 : 0;
        g_inv[idx] = bad ? 1.f : 0.f;
    }
    __syncthreads();

    float4* out = (float4*)&g_ctx[(size_t)idx * (2 * Kk)];   // 222 float4
    const float4 zero4 = make_float4(0.f, 0.f, 0.f, 0.f);
    if (inval) {
        for (int t = tid; t < 222; t += 128) out[t] = zero4;
        if (wavg_out && tid < Nn) wavg_out[idx * Nn + tid] = 0.f;
        return;
    }
    for (int t = tid; t < 222; t += 128) {
        const int h = (t >= 111) ? 1 : 0;
        float4 v = zero4;
        #pragma unroll
        for (int s = 0; s < 4; ++s) {
            const float4 p = ((const float4*)&g_pctx[((size_t)idx * 4 + s) * (2 * Kk)])[t];
            const float f = fs[s][h];
            v.x += f * p.x; v.y += f * p.y; v.z += f * p.z; v.w += f * p.w;
        }
        out[t] = v;
    }
    if (wavg_out && tid < Nn) {
        const int s = tid >> 4, p = tid & 15;
        const float w0 = g_pw[((size_t)idx * 4 + s) * 32 + p]      * fs[s][0];
        const float w1 = g_pw[((size_t)idx * 4 + s) * 32 + 16 + p] * fs[s][1];
        wavg_out[idx * Nn + tid] = 0.5f * (w0 + w1);
    }
}

// ==================== launch ====================
extern "C" void kernel_launch(void* const* d_in, const int* in_sizes, int n_in,
                              void* d_out, int out_size)
{
    const float* src_node = (const float*)d_in[0];
    const float* src_time = (const float*)d_in[1];
    const float* nf       = (const float*)d_in[2];
    const float* nt       = (const float*)d_in[3];
    const float* ef       = (const float*)d_in[4];
    const void*  mask     = d_in[5];
    const float* Wq = (const float*)d_in[6];
    const float* Wk = (const float*)d_in[7];
    const float* Wv = (const float*)d_in[8];
    const float* bq = (const float*)d_in[9];
    // bk dropped: softmax-invariant
    const float* bv = (const float*)d_in[11];
    const float* Wo = (const float*)d_in[12];
    const float* bo = (const float*)d_in[13];
    const float* W1 = (const float*)d_in[14];
    const float* b1 = (const float*)d_in[15];
    const float* W2 = (const float*)d_in[16];
    const float* b2 = (const float*)d_in[17];

    float* merged = (float*)d_out;
    float* wavg = nullptr;
    if (out_size >= Bn * OUTF + Bn * Rr * Nn)
        wavg = merged + Bn * OUTF;

    float *pX, *pq, *pqk, *pctx, *pattn, *pcat, *ph1, *pinv, *pf1, *pf2;
    cudaGetSymbolAddress((void**)&pX,    g_X);
    cudaGetSymbolAddress((void**)&pq,    g_q);
    cudaGetSymbolAddress((void**)&pqk,   g_qk);
    cudaGetSymbolAddress((void**)&pctx,  g_ctx);
    cudaGetSymbolAddress((void**)&pattn, g_attn);
    cudaGetSymbolAddress((void**)&pcat,  g_cat);
    cudaGetSymbolAddress((void**)&ph1,   g_h1);
    cudaGetSymbolAddress((void**)&pinv,  g_inv);
    cudaGetSymbolAddress((void**)&pf1,   g_f1p);
    cudaGetSymbolAddress((void**)&pf2,   g_f2p);

    // prep + mask-dtype detect (extra block)
    prep_X_kernel<<<Bn + 1, 256>>>(src_node, src_time, (const unsigned int*)mask);

    // q = X @ Wq[r]^T + bq   (NT, z=r)
    {
        dim3 g(Bn / 64, (Ee + 63) / 64, Rr);
        gemm_tc_kernel<true><<<g, 128>>>(pX, Ee, 0,
                                         Wq, Ee, (long)Ee * Ee,
                                         pq, Rr * Ee, Ee,
                                         bq, Ee, nullptr, 0,
                                         Ee, Ee, 0, 0);
    }
    // qk = q_h @ Wk_h   (NN, z=2r+h)
    {
        dim3 g(Bn / 64, (Kk + 63) / 64, Rr * 2);
        gemm_tc_kernel<false><<<g, 128>>>(pq, Rr * Ee, Dhh,
                                          Wk, Kk, (long)Dhh * Kk,
                                          pqk, Rr * 2 * Kk, Kk,
                                          nullptr, 0, nullptr, 0,
                                          Kk, Dhh, 0, 0);
    }
    // attention: 4-way split (R10) + merge
    {
        dim3 g(Bn, Rr, 4);
        attn_q_kernel<<<g, 128>>>(nf, nt, ef, mask);
        merge4_kernel<<<Bn * Rr, 128>>>(wavg);
    }
    // attn = ctx @ Wv_h^T + bv   (NT, z=2r+h)
    {
        dim3 g(Bn / 64, (Dhh + 63) / 64, Rr * 2);
        gemm_tc_kernel<true><<<g, 128>>>(pctx, Rr * 2 * Kk, Kk,
                                         Wv, Kk, (long)Dhh * Kk,
                                         pattn, Rr * Ee, Dhh,
                                         bv, Dhh, nullptr, 0,
                                         Dhh, Kk, 0, 0);
    }
    // out = attn @ Wo[r]^T + bo, zero where invalid -> g_cat  (NT, epi 2)
    {
        dim3 g(Bn / 64, (Ee + 63) / 64, Rr);
        gemm_tc_kernel<true><<<g, 128>>>(pattn, Rr * Ee, Ee,
                                         Wo, Ee, (long)Ee * Ee,
                                         pcat, CATN, Ee,
                                         bo, Ee,
                                         pinv, Rr,
                                         Ee, Ee, 2, 0);
    }
    // fc1: splitK-12 partials, then reduce(+bias,+relu)
    {
        dim3 g(Bn / 64, (OUTF + 63) / 64, F1SPLIT);
        gemm_tc_kernel<true><<<g, 128>>>(pcat, CATN, 0,
                                         W1, CATN, 0,
                                         pf1, OUTF, (long)Bn * OUTF,
                                         nullptr, 0, nullptr, 0,
                                         OUTF, CATN, 3, F1CHUNK);
        reduce_kernel<<<(Bn * OUTF + 255) / 256, 256>>>(pf1, F1SPLIT, Bn * OUTF, OUTF, b1, 1, ph1);
    }
    // fc2: splitK-4 partials, then reduce(+bias)
    {
        dim3 g(Bn / 64, (OUTF + 63) / 64, F2SPLIT);
        gemm_tc_kernel<true><<<g, 128>>>(ph1, OUTF, 0,
                                         W2, OUTF, 0,
                                         pf2, OUTF, (long)Bn * OUTF,
                                         nullptr, 0, nullptr, 0,
                                         OUTF, OUTF, 3, F2CHUNK);
        reduce_kernel<<<(Bn * OUTF + 255) / 256, 256>>>(pf2, F2SPLIT, Bn * OUTF, OUTF, b2, 0, merged);
    }
}

// round 16
// speedup vs baseline: 1.4174x; 1.4174x over previous
#include <cuda_runtime.h>
#include <math.h>
#include <stdint.h>

// Problem constants
#define Bn   512
#define Rr   5
#define Nn   64
#define Ff   172
#define Tt   100
#define Ee   272     // F + T
#define Kk   444     // F + EF + T
#define Dhh  136     // E / H
#define OUTF 172
#define CATN 1532    // R*E + F
#define QRT  16      // neighbor rows per attention CTA
#define F1SPLIT 12
#define F1CHUNK 128
#define F2SPLIT 4
#define F2CHUNK 44

// ---------------- inter-kernel scratch ----------------
__device__ __align__(256) float g_X[Bn * Ee];
__device__ __align__(256) float g_q[Bn * Rr * Ee];
__device__ __align__(256) float g_qk[Bn * Rr * 2 * Kk];
__device__ __align__(256) float g_ctx[Bn * Rr * 2 * Kk];
__device__ __align__(256) float g_attn[Bn * Rr * Ee];
__device__ __align__(256) float g_cat[Bn * CATN];
__device__ __align__(256) float g_h1[Bn * OUTF];
__device__ __align__(256) float g_inv[Bn * Rr];
__device__ int g_mask_u8;
// attention partials
__device__ __align__(256) float g_pctx[Bn * Rr * 4 * 2 * Kk];
__device__ __align__(256) float g_pml [Bn * Rr * 4 * 4];
__device__ __align__(256) float g_pw  [Bn * Rr * 4 * 2 * QRT];
// split-K partials
__device__ __align__(256) float g_f1p[F1SPLIT * Bn * OUTF];
__device__ __align__(256) float g_f2p[F2SPLIT * Bn * OUTF];

__device__ __forceinline__ float warp_reduce(float v) {
    #pragma unroll
    for (int o = 16; o; o >>= 1) v += __shfl_down_sync(0xffffffffu, v, o);
    return v;
}
__device__ __forceinline__ float dot4(float4 a, float4 b) {
    return a.x * b.x + a.y * b.y + a.z * b.z + a.w * b.w;
}
__device__ __forceinline__ void cp_async16(void* sdst, const void* gsrc) {
    unsigned int saddr = (unsigned int)__cvta_generic_to_shared(sdst);
    asm volatile("cp.async.cg.shared.global [%0], [%1], 16;\n"
                 :: "r"(saddr), "l"(gsrc));
}
__device__ __forceinline__ void cp_commit() {
    asm volatile("cp.async.commit_group;\n");
}
template<int N>
__device__ __forceinline__ void cp_wait() {
    asm volatile("cp.async.wait_group %0;\n" :: "n"(N));
}

// ==================== prep (+ mask dtype detect in extra block) ====================
__global__ __launch_bounds__(256)
void prep_X_kernel(const float* __restrict__ src_node,
                   const float* __restrict__ src_time,
                   const unsigned int* __restrict__ mask_words)
{
    const int b = blockIdx.x, tid = threadIdx.x;
    if (b == Bn) {
        const int nwords = 8192;
        unsigned int acc = 0;
        for (int i = tid; i < nwords; i += 256) acc |= mask_words[i];
        __shared__ unsigned int red[8];
        unsigned int v = acc;
        #pragma unroll
        for (int o = 16; o; o >>= 1) v |= __shfl_xor_sync(0xffffffffu, v, o);
        if ((tid & 31) == 0) red[tid >> 5] = v;
        __syncthreads();
        if (tid == 0) {
            unsigned int t = 0;
            #pragma unroll
            for (int w = 0; w < 8; ++w) t |= red[w];
            g_mask_u8 = (t > 1u) ? 1 : 0;
        }
        return;
    }
    for (int e = tid; e < Ee; e += 256)
        g_X[b * Ee + e] = (e < Ff) ? src_node[b * Ff + e]
                                   : src_time[b * Tt + (e - Ff)];
    for (int j = tid; j < Ff; j += 256)
        g_cat[b * CATN + Rr * Ee + j] = src_node[b * Ff + j];
}

// ==================== GEMM (R8 config): 128 thr, 64x64, 8x4 micro ====================
template<bool BT>
__global__ __launch_bounds__(128, 4)
void gemm2_kernel(const float* __restrict__ A, int lda, long strideAz,
                  const float* __restrict__ B, int ldb, long strideBz,
                  float* __restrict__ C, int ldc, long strideCz,
                  const float* __restrict__ bias, long strideBiasZ,
                  const float* __restrict__ invf, int invRowStride,
                  int N, int K, int epi, int kChunk)
{
    __shared__ float As[16][68];
    __shared__ float Bs[16][68];
    const int z = blockIdx.z;
    int Keff = K;
    if (kChunk > 0) {
        const int ko = z * kChunk;
        Keff = min(kChunk, K - ko);
        A += ko;
        B += BT ? (long)ko : (long)ko * ldb;
    } else {
        A += (size_t)z * strideAz;
        B += (size_t)z * strideBz;
    }
    C += (size_t)z * strideCz;
    const float* bz = bias ? bias + (size_t)z * strideBiasZ : nullptr;
    const int m0 = blockIdx.x * 64, n0 = blockIdx.y * 64;
    const int tid = threadIdx.x;
    const int tn = tid & 15, tm = tid >> 4;

    float acc[8][4];
    #pragma unroll
    for (int i = 0; i < 8; ++i)
        #pragma unroll
        for (int j = 0; j < 4; ++j) acc[i][j] = 0.f;

    for (int k0 = 0; k0 < Keff; k0 += 16) {
        {
            const int c = tid & 3, mbase = tid >> 2;
            #pragma unroll
            for (int i = 0; i < 2; ++i) {
                const int mm = mbase + 32 * i;
                const int k = k0 + 4 * c;
                float4 v = make_float4(0.f, 0.f, 0.f, 0.f);
                if (k < Keff) v = *(const float4*)&A[(size_t)(m0 + mm) * lda + k];
                As[4 * c + 0][mm] = v.x;
                As[4 * c + 1][mm] = v.y;
                As[4 * c + 2][mm] = v.z;
                As[4 * c + 3][mm] = v.w;
            }
        }
        if (BT) {
            const int c = tid & 3, nbase = tid >> 2;
            #pragma unroll
            for (int i = 0; i < 2; ++i) {
                const int nn = nbase + 32 * i;
                const int k = k0 + 4 * c;
                float4 v = make_float4(0.f, 0.f, 0.f, 0.f);
                if (k < Keff && (n0 + nn) < N)
                    v = *(const float4*)&B[(size_t)(n0 + nn) * ldb + k];
                Bs[4 * c + 0][nn] = v.x;
                Bs[4 * c + 1][nn] = v.y;
                Bs[4 * c + 2][nn] = v.z;
                Bs[4 * c + 3][nn] = v.w;
            }
        } else {
            const int n4 = (tid & 15) * 4, kb = tid >> 4;
            #pragma unroll
            for (int i = 0; i < 2; ++i) {
                const int k = kb + 8 * i;
                float4 v = make_float4(0.f, 0.f, 0.f, 0.f);
                if ((k0 + k) < Keff && (n0 + n4) < N)
                    v = *(const float4*)&B[(size_t)(k0 + k) * ldb + n0 + n4];
                *(float4*)&Bs[k][n4] = v;
            }
        }
        __syncthreads();
        #pragma unroll
        for (int kt = 0; kt < 16; ++kt) {
            const float4 a0 = *(const float4*)&As[kt][tm * 8];
            const float4 a1 = *(const float4*)&As[kt][tm * 8 + 4];
            const float4 b4 = *(const float4*)&Bs[kt][tn * 4];
            const float av[8] = {a0.x, a0.y, a0.z, a0.w, a1.x, a1.y, a1.z, a1.w};
            const float bw[4] = {b4.x, b4.y, b4.z, b4.w};
            #pragma unroll
            for (int i = 0; i < 8; ++i)
                #pragma unroll
                for (int j = 0; j < 4; ++j)
                    acc[i][j] += av[i] * bw[j];
        }
        __syncthreads();
    }

    #pragma unroll
    for (int i = 0; i < 8; ++i) {
        const int row = m0 + tm * 8 + i;
        float vmul = 1.f;
        if (epi == 2 && invf)
            vmul = (invf[z + (size_t)row * invRowStride] > 0.5f) ? 0.f : 1.f;
        #pragma unroll
        for (int j = 0; j < 4; ++j) {
            const int col = n0 + tn * 4 + j;
            if (col < N) {
                float v = acc[i][j];
                if (epi != 3 && bz) v += bz[col];
                if (epi == 1) v = fmaxf(v, 0.f);
                if (epi == 2) v *= vmul;
                C[(size_t)row * ldc + col] = v;
            }
        }
    }
}

// ==================== splitK reduce ====================
__global__ void reduce_kernel(const float* __restrict__ P, int nsplit, int total,
                              int ncol, const float* __restrict__ bias, int relu,
                              float* __restrict__ out)
{
    const int i = blockIdx.x * 256 + threadIdx.x;
    if (i < total) {
        float s = bias[i % ncol];
        for (int z = 0; z < nsplit; ++z) s += P[(size_t)z * total + i];
        if (relu) s = fmaxf(s, 0.f);
        out[i] = s;
    }
}

// ==================== attention: 4-way split, cp.async 2-group pipelined load ====
#define AK_LD  444                  // row stride floats = 111 float4 (16B aligned)
#define NSEG_F 43
#define NSEG_T 25
#define HB_A   (8 * NSEG_F)         // 344 f4: neigh seg per 8-row batch
#define HB_TOT (8 * (2 * NSEG_F + NSEG_T))   // 888 f4 per 8-row batch

__global__ __launch_bounds__(128, 7)
void attn_q_kernel(const float* __restrict__ neigh_feat,
                   const float* __restrict__ neigh_time,
                   const float* __restrict__ edge_feat,
                   const void* __restrict__ mask_raw)
{
    __shared__ float kin[QRT * AK_LD];     // 28416 B
    __shared__ float ssm[2][QRT];
    __shared__ float ws[2][QRT];
    __shared__ float msk[QRT];

    const int b = blockIdx.x, r = blockIdx.y, qrt = blockIdx.z;
    const int idx = b * Rr + r;
    const int n0 = qrt * QRT;
    const int tid = threadIdx.x;
    const int lane = tid & 31, warp = tid >> 5;
    const float4 zero4 = make_float4(0.f, 0.f, 0.f, 0.f);
    const float scale = rsqrtf((float)Dhh);

    // ---- issue cp.async for batch (8 rows) into kin rows [8*batch, 8*batch+8) ----
    auto prefetch8 = [&](int batch) {
        const int nb = n0 + batch * 8;
        const float4* pa = (const float4*)(neigh_feat + ((size_t)idx * Nn + nb) * Ff);
        const float4* pb = (const float4*)(edge_feat  + ((size_t)idx * Nn + nb) * Ff);
        const float4* pc = (const float4*)(neigh_time + ((size_t)idx * Nn + nb) * Tt);
        #pragma unroll
        for (int it = 0; it < 7; ++it) {
            const int t = tid + it * 128;
            if (t < HB_TOT) {
                const float4* src;
                int row, col;
                if (t < HB_A) {
                    row = t / NSEG_F; const int s = t - row * NSEG_F;
                    col = s * 4; src = &pa[row * NSEG_F + s];
                } else if (t < 2 * HB_A) {
                    const int t2 = t - HB_A;
                    row = t2 / NSEG_F; const int s = t2 - row * NSEG_F;
                    col = Ff + s * 4; src = &pb[row * NSEG_F + s];
                } else {
                    const int t2 = t - 2 * HB_A;
                    row = t2 / NSEG_T; const int s = t2 - row * NSEG_T;
                    col = 2 * Ff + s * 4; src = &pc[row * NSEG_T + s];
                }
                cp_async16(&kin[(batch * 8 + row) * AK_LD + col], src);
            }
        }
        cp_commit();
    };

    prefetch8(0);
    prefetch8(1);

    // mask + qk coefficients overlap the async copies
    if (tid < QRT) {
        const int mi = (r * Bn + b) * Nn + n0 + tid;
        int mv;
        if (g_mask_u8) mv = ((const unsigned char*)mask_raw)[mi];
        else           mv = ((const int*)mask_raw)[mi];
        msk[tid] = (mv != 0) ? 1.f : 0.f;
    }
    float4 q0[4], q1[4];
    {
        const float4* qkg4 = (const float4*)&g_qk[(size_t)idx * (2 * Kk)];
        #pragma unroll
        for (int k = 0; k < 4; ++k) {
            const int c = lane + 32 * k;
            const bool ok = (c < 111);
            q0[k] = ok ? qkg4[c]       : zero4;
            q1[k] = ok ? qkg4[111 + c] : zero4;
        }
    }

    // ---- scores for one 8-row batch: warp w -> rows batch*8 + {2w, 2w+1} ----
    auto score8 = [&](int batch) {
        #pragma unroll
        for (int i = 0; i < 2; ++i) {
            const int nl = batch * 8 + warp * 2 + i;
            const float4* krow = (const float4*)&kin[nl * AK_LD];
            float a0 = 0.f, a1 = 0.f;
            #pragma unroll
            for (int k = 0; k < 3; ++k) {
                const float4 v = krow[lane + 32 * k];
                a0 += dot4(v, q0[k]);
                a1 += dot4(v, q1[k]);
            }
            if (lane < 15) {
                const float4 v = krow[lane + 96];
                a0 += dot4(v, q0[3]);
                a1 += dot4(v, q1[3]);
            }
            a0 = warp_reduce(a0);
            a1 = warp_reduce(a1);
            if (lane == 0) {
                const bool pad = msk[nl] > 0.5f;
                ssm[0][nl] = pad ? -1e30f : a0 * scale;
                ssm[1][nl] = pad ? -1e30f : a1 * scale;
            }
        }
    };

    cp_wait<1>();          // batch-0 copies issued by this thread done
    __syncthreads();       // all threads' batch-0 data + msk visible
    score8(0);             // compute rows 0-7 while rows 8-15 still in flight
    cp_wait<0>();
    __syncthreads();       // batch-1 visible (and batch-0 ssm writes ordered)
    score8(1);
    __syncthreads();

    // local flash stats over 16 rows (warp 0; lanes 0..15 -> h0, 16..31 -> h1)
    if (warp == 0) {
        const int h = lane >> 4, p = lane & 15;
        float s = ssm[h][p];
        float m = s;
        #pragma unroll
        for (int o = 8; o; o >>= 1) m = fmaxf(m, __shfl_xor_sync(0xffffffffu, m, o));
        const float e = (msk[p] > 0.5f) ? 0.f : __expf(s - m);
        float l = e;
        #pragma unroll
        for (int o = 8; o; o >>= 1) l += __shfl_xor_sync(0xffffffffu, l, o);
        ws[h][p] = e;
        g_pw[((size_t)idx * 4 + qrt) * 32 + h * 16 + p] = e;
        if (p == 0) {
            g_pml[((size_t)idx * 4 + qrt) * 4 + h * 2 + 0] = m;
            g_pml[((size_t)idx * 4 + qrt) * 4 + h * 2 + 1] = l;
        }
    }
    __syncthreads();

    // partial ctx: one float4 column per thread (LDS.128)
    if (tid < 111) {
        float* pout = &g_pctx[((size_t)idx * 4 + qrt) * (2 * Kk)];
        float4 acc0 = zero4, acc1 = zero4;
        #pragma unroll
        for (int n = 0; n < QRT; ++n) {
            const float4 v = *(const float4*)&kin[n * AK_LD + 4 * tid];
            const float w0 = ws[0][n], w1 = ws[1][n];
            acc0.x += w0 * v.x; acc0.y += w0 * v.y;
            acc0.z += w0 * v.z; acc0.w += w0 * v.w;
            acc1.x += w1 * v.x; acc1.y += w1 * v.y;
            acc1.z += w1 * v.z; acc1.w += w1 * v.w;
        }
        *(float4*)&pout[4 * tid]      = acc0;
        *(float4*)&pout[Kk + 4 * tid] = acc1;
    }
}

// ==================== merge 4 quarters (float4) ====================
__global__ __launch_bounds__(128)
void merge4_kernel(float* __restrict__ wavg_out)
{
    const int idx = blockIdx.x;
    const int tid = threadIdx.x;
    __shared__ float fs[4][2];
    __shared__ int inval;

    if (tid == 0) {
        bool bad = false;
        #pragma unroll
        for (int h = 0; h < 2; ++h) {
            float m[4], l[4];
            float M = -1e38f;
            #pragma unroll
            for (int s = 0; s < 4; ++s) {
                m[s] = g_pml[((size_t)idx * 4 + s) * 4 + h * 2 + 0];
                l[s] = g_pml[((size_t)idx * 4 + s) * 4 + h * 2 + 1];
                M = fmaxf(M, m[s]);
            }
            float L = 0.f, e[4];
            #pragma unroll
            for (int s = 0; s < 4; ++s) { e[s] = __expf(m[s] - M); L += l[s] * e[s]; }
            if (L <= 0.f) { bad = true; fs[0][h] = fs[1][h] = fs[2][h] = fs[3][h] = 0.f; }
            else {
                const float inv = 1.f / L;
                #pragma unroll
                for (int s = 0; s < 4; ++s) fs[s][h] = e[s] * inv;
            }
        }
        inval = bad ? 1 : 0;
        g_inv[idx] = bad ? 1.f : 0.f;
    }
    __syncthreads();

    float4* out = (float4*)&g_ctx[(size_t)idx * (2 * Kk)];   // 222 float4
    const float4 zero4 = make_float4(0.f, 0.f, 0.f, 0.f);
    if (inval) {
        for (int t = tid; t < 222; t += 128) out[t] = zero4;
        if (wavg_out && tid < Nn) wavg_out[idx * Nn + tid] = 0.f;
        return;
    }
    for (int t = tid; t < 222; t += 128) {
        const int h = (t >= 111) ? 1 : 0;
        float4 v = zero4;
        #pragma unroll
        for (int s = 0; s < 4; ++s) {
            const float4 p = ((const float4*)&g_pctx[((size_t)idx * 4 + s) * (2 * Kk)])[t];
            const float f = fs[s][h];
            v.x += f * p.x; v.y += f * p.y; v.z += f * p.z; v.w += f * p.w;
        }
        out[t] = v;
    }
    if (wavg_out && tid < Nn) {
        const int s = tid >> 4, p = tid & 15;
        const float w0 = g_pw[((size_t)idx * 4 + s) * 32 + p]      * fs[s][0];
        const float w1 = g_pw[((size_t)idx * 4 + s) * 32 + 16 + p] * fs[s][1];
        wavg_out[idx * Nn + tid] = 0.5f * (w0 + w1);
    }
}

// ==================== launch ====================
extern "C" void kernel_launch(void* const* d_in, const int* in_sizes, int n_in,
                              void* d_out, int out_size)
{
    const float* src_node = (const float*)d_in[0];
    const float* src_time = (const float*)d_in[1];
    const float* nf       = (const float*)d_in[2];
    const float* nt       = (const float*)d_in[3];
    const float* ef       = (const float*)d_in[4];
    const void*  mask     = d_in[5];
    const float* Wq = (const float*)d_in[6];
    const float* Wk = (const float*)d_in[7];
    const float* Wv = (const float*)d_in[8];
    const float* bq = (const float*)d_in[9];
    // bk dropped: softmax-invariant
    const float* bv = (const float*)d_in[11];
    const float* Wo = (const float*)d_in[12];
    const float* bo = (const float*)d_in[13];
    const float* W1 = (const float*)d_in[14];
    const float* b1 = (const float*)d_in[15];
    const float* W2 = (const float*)d_in[16];
    const float* b2 = (const float*)d_in[17];

    float* merged = (float*)d_out;
    float* wavg = nullptr;
    if (out_size >= Bn * OUTF + Bn * Rr * Nn)
        wavg = merged + Bn * OUTF;

    float *pX, *pq, *pqk, *pctx, *pattn, *pcat, *ph1, *pinv, *pf1, *pf2;
    cudaGetSymbolAddress((void**)&pX,    g_X);
    cudaGetSymbolAddress((void**)&pq,    g_q);
    cudaGetSymbolAddress((void**)&pqk,   g_qk);
    cudaGetSymbolAddress((void**)&pctx,  g_ctx);
    cudaGetSymbolAddress((void**)&pattn, g_attn);
    cudaGetSymbolAddress((void**)&pcat,  g_cat);
    cudaGetSymbolAddress((void**)&ph1,   g_h1);
    cudaGetSymbolAddress((void**)&pinv,  g_inv);
    cudaGetSymbolAddress((void**)&pf1,   g_f1p);
    cudaGetSymbolAddress((void**)&pf2,   g_f2p);

    // prep + mask-dtype detect (extra block)
    prep_X_kernel<<<Bn + 1, 256>>>(src_node, src_time, (const unsigned int*)mask);

    // q = X @ Wq[r]^T + bq   (NT, z=r)
    {
        dim3 g(Bn / 64, (Ee + 63) / 64, Rr);
        gemm2_kernel<true><<<g, 128>>>(pX, Ee, 0,
                                       Wq, Ee, (long)Ee * Ee,
                                       pq, Rr * Ee, Ee,
                                       bq, Ee, nullptr, 0,
                                       Ee, Ee, 0, 0);
    }
    // qk = q_h @ Wk_h   (NN, z=2r+h)
    {
        dim3 g(Bn / 64, (Kk + 63) / 64, Rr * 2);
        gemm2_kernel<false><<<g, 128>>>(pq, Rr * Ee, Dhh,
                                        Wk, Kk, (long)Dhh * Kk,
                                        pqk, Rr * 2 * Kk, Kk,
                                        nullptr, 0, nullptr, 0,
                                        Kk, Dhh, 0, 0);
    }
    // attention: 4-way split (pipelined load) + merge
    {
        dim3 g(Bn, Rr, 4);
        attn_q_kernel<<<g, 128>>>(nf, nt, ef, mask);
        merge4_kernel<<<Bn * Rr, 128>>>(wavg);
    }
    // attn = ctx @ Wv_h^T + bv   (NT, z=2r+h)
    {
        dim3 g(Bn / 64, (Dhh + 63) / 64, Rr * 2);
        gemm2_kernel<true><<<g, 128>>>(pctx, Rr * 2 * Kk, Kk,
                                       Wv, Kk, (long)Dhh * Kk,
                                       pattn, Rr * Ee, Dhh,
                                       bv, Dhh, nullptr, 0,
                                       Dhh, Kk, 0, 0);
    }
    // out = attn @ Wo[r]^T + bo, zero where invalid -> g_cat  (NT, epi 2)
    {
        dim3 g(Bn / 64, (Ee + 63) / 64, Rr);
        gemm2_kernel<true><<<g, 128>>>(pattn, Rr * Ee, Ee,
                                       Wo, Ee, (long)Ee * Ee,
                                       pcat, CATN, Ee,
                                       bo, Ee,
                                       pinv, Rr,
                                       Ee, Ee, 2, 0);
    }
    // fc1: splitK-12 partials, then reduce(+bias,+relu)
    {
        dim3 g(Bn / 64, (OUTF + 63) / 64, F1SPLIT);
        gemm2_kernel<true><<<g, 128>>>(pcat, CATN, 0,
                                       W1, CATN, 0,
                                       pf1, OUTF, (long)Bn * OUTF,
                                       nullptr, 0, nullptr, 0,
                                       OUTF, CATN, 3, F1CHUNK);
        reduce_kernel<<<(Bn * OUTF + 255) / 256, 256>>>(pf1, F1SPLIT, Bn * OUTF, OUTF, b1, 1, ph1);
    }
    // fc2: splitK-4 partials, then reduce(+bias)
    {
        dim3 g(Bn / 64, (OUTF + 63) / 64, F2SPLIT);
        gemm2_kernel<true><<<g, 128>>>(ph1, OUTF, 0,
                                       W2, OUTF, 0,
                                       pf2, OUTF, (long)Bn * OUTF,
                                       nullptr, 0, nullptr, 0,
                                       OUTF, OUTF, 3, F2CHUNK);
        reduce_kernel<<<(Bn * OUTF + 255) / 256, 256>>>(pf2, F2SPLIT, Bn * OUTF, OUTF, b2, 0, merged);
    }
}

// round 17
// speedup vs baseline: 1.5853x; 1.1185x over previous
#include <cuda_runtime.h>
#include <math.h>
#include <stdint.h>

// Problem constants
#define Bn   512
#define Rr   5
#define Nn   64
#define Ff   172
#define Tt   100
#define Ee   272     // F + T
#define Kk   444     // F + EF + T
#define Dhh  136     // E / H
#define OUTF 172
#define CATN 1532    // R*E + F
#define QRT  16      // neighbor rows per attention CTA
#define F1SPLIT 12
#define F1CHUNK 128
#define F2SPLIT 4
#define F2CHUNK 44

// ---------------- inter-kernel scratch ----------------
__device__ __align__(256) float g_X[Bn * Ee];
__device__ __align__(256) float g_q[Bn * Rr * Ee];
__device__ __align__(256) float g_qk[Bn * Rr * 2 * Kk];
__device__ __align__(256) float g_ctx[Bn * Rr * 2 * Kk];
__device__ __align__(256) float g_attn[Bn * Rr * Ee];
__device__ __align__(256) float g_cat[Bn * CATN];
__device__ __align__(256) float g_h1[Bn * OUTF];
__device__ __align__(256) float g_inv[Bn * Rr];
__device__ int g_mask_u8;
// attention partials
__device__ __align__(256) float g_pctx[Bn * Rr * 4 * 2 * Kk];
__device__ __align__(256) float g_pml [Bn * Rr * 4 * 4];
__device__ __align__(256) float g_pw  [Bn * Rr * 4 * 2 * QRT];
// split-K partials
__device__ __align__(256) float g_f1p[F1SPLIT * Bn * OUTF];
__device__ __align__(256) float g_f2p[F2SPLIT * Bn * OUTF];

__device__ __forceinline__ float warp_reduce(float v) {
    #pragma unroll
    for (int o = 16; o; o >>= 1) v += __shfl_down_sync(0xffffffffu, v, o);
    return v;
}
__device__ __forceinline__ float dot4(float4 a, float4 b) {
    return a.x * b.x + a.y * b.y + a.z * b.z + a.w * b.w;
}
__device__ __forceinline__ void cp_async16(void* sdst, const void* gsrc) {
    unsigned int saddr = (unsigned int)__cvta_generic_to_shared(sdst);
    asm volatile("cp.async.cg.shared.global [%0], [%1], 16;\n"
                 :: "r"(saddr), "l"(gsrc));
}
__device__ __forceinline__ void cp_commit() {
    asm volatile("cp.async.commit_group;\n");
}
template<int N>
__device__ __forceinline__ void cp_wait() {
    asm volatile("cp.async.wait_group %0;\n" :: "n"(N));
}

// ==================== prep (+ mask dtype detect in extra block) ====================
__global__ __launch_bounds__(256)
void prep_X_kernel(const float* __restrict__ src_node,
                   const float* __restrict__ src_time,
                   const unsigned int* __restrict__ mask_words)
{
    const int b = blockIdx.x, tid = threadIdx.x;
    if (b == Bn) {
        const int nwords = 8192;
        unsigned int acc = 0;
        for (int i = tid; i < nwords; i += 256) acc |= mask_words[i];
        __shared__ unsigned int red[8];
        unsigned int v = acc;
        #pragma unroll
        for (int o = 16; o; o >>= 1) v |= __shfl_xor_sync(0xffffffffu, v, o);
        if ((tid & 31) == 0) red[tid >> 5] = v;
        __syncthreads();
        if (tid == 0) {
            unsigned int t = 0;
            #pragma unroll
            for (int w = 0; w < 8; ++w) t |= red[w];
            g_mask_u8 = (t > 1u) ? 1 : 0;
        }
        return;
    }
    for (int e = tid; e < Ee; e += 256)
        g_X[b * Ee + e] = (e < Ff) ? src_node[b * Ff + e]
                                   : src_time[b * Tt + (e - Ff)];
    for (int j = tid; j < Ff; j += 256)
        g_cat[b * CATN + Rr * Ee + j] = src_node[b * Ff + j];
}

// ==================== GEMM: 128 thr, 64x64, 8x4 micro, double-buffered ====================
// BT=true: B row-major [N,K] (NT); BT=false: B row-major [K,N] (NN)
// epi: 0=bias, 1=bias+relu, 2=bias+zero-if-invalid, 3=raw partial (splitK)
// Register-staged LDG for tile t+1 overlaps compute of tile t.
// launch_bounds(128,4): reg cap 128 -> no spill of the 16-float staging.
template<bool BT>
__global__ __launch_bounds__(128, 4)
void gemm2_kernel(const float* __restrict__ A, int lda, long strideAz,
                  const float* __restrict__ B, int ldb, long strideBz,
                  float* __restrict__ C, int ldc, long strideCz,
                  const float* __restrict__ bias, long strideBiasZ,
                  const float* __restrict__ invf, int invRowStride,
                  int N, int K, int epi, int kChunk)
{
    __shared__ float As[2][16][68];
    __shared__ float Bs[2][16][68];
    const int z = blockIdx.z;
    int Keff = K;
    if (kChunk > 0) {
        const int ko = z * kChunk;
        Keff = min(kChunk, K - ko);
        A += ko;
        B += BT ? (long)ko : (long)ko * ldb;
    } else {
        A += (size_t)z * strideAz;
        B += (size_t)z * strideBz;
    }
    C += (size_t)z * strideCz;
    const float* bz = bias ? bias + (size_t)z * strideBiasZ : nullptr;
    const int m0 = blockIdx.x * 64, n0 = blockIdx.y * 64;
    const int tid = threadIdx.x;
    const int tn = tid & 15, tm = tid >> 4;
    const float4 zero4 = make_float4(0.f, 0.f, 0.f, 0.f);

    const int ac = tid & 3, am = tid >> 2;          // A/BT-B: k-quad, row base
    const int bn4 = (tid & 15) * 4, bk = tid >> 4;  // NN-B: col4, k base
    const int nTiles = (Keff + 15) >> 4;

    float4 ra[2], rb[2];

    auto ldg_tile = [&](int t) {
        const int k0 = t << 4;
        {
            const int k = k0 + 4 * ac;
            #pragma unroll
            for (int i = 0; i < 2; ++i) {
                const int mm = am + 32 * i;
                ra[i] = (k < Keff) ? *(const float4*)&A[(size_t)(m0 + mm) * lda + k]
                                   : zero4;
            }
        }
        if (BT) {
            const int k = k0 + 4 * ac;
            #pragma unroll
            for (int i = 0; i < 2; ++i) {
                const int nn = am + 32 * i;
                rb[i] = (k < Keff && (n0 + nn) < N)
                        ? *(const float4*)&B[(size_t)(n0 + nn) * ldb + k] : zero4;
            }
        } else {
            #pragma unroll
            for (int i = 0; i < 2; ++i) {
                const int k = k0 + bk + 8 * i;
                rb[i] = (k < Keff && (n0 + bn4) < N)
                        ? *(const float4*)&B[(size_t)k * ldb + n0 + bn4] : zero4;
            }
        }
    };
    auto sts_tile = [&](int buf) {
        #pragma unroll
        for (int i = 0; i < 2; ++i) {
            const int mm = am + 32 * i;
            As[buf][4 * ac + 0][mm] = ra[i].x;
            As[buf][4 * ac + 1][mm] = ra[i].y;
            As[buf][4 * ac + 2][mm] = ra[i].z;
            As[buf][4 * ac + 3][mm] = ra[i].w;
        }
        if (BT) {
            #pragma unroll
            for (int i = 0; i < 2; ++i) {
                const int nn = am + 32 * i;
                Bs[buf][4 * ac + 0][nn] = rb[i].x;
                Bs[buf][4 * ac + 1][nn] = rb[i].y;
                Bs[buf][4 * ac + 2][nn] = rb[i].z;
                Bs[buf][4 * ac + 3][nn] = rb[i].w;
            }
        } else {
            #pragma unroll
            for (int i = 0; i < 2; ++i)
                *(float4*)&Bs[buf][bk + 8 * i][bn4] = rb[i];
        }
    };

    float acc[8][4];
    #pragma unroll
    for (int i = 0; i < 8; ++i)
        #pragma unroll
        for (int j = 0; j < 4; ++j) acc[i][j] = 0.f;

    ldg_tile(0);
    sts_tile(0);
    __syncthreads();

    for (int t = 0; t < nTiles; ++t) {
        const int cur = t & 1;
        if (t + 1 < nTiles) ldg_tile(t + 1);   // overlaps compute below
        #pragma unroll
        for (int kt = 0; kt < 16; ++kt) {
            const float4 a0 = *(const float4*)&As[cur][kt][tm * 8];
            const float4 a1 = *(const float4*)&As[cur][kt][tm * 8 + 4];
            const float4 b4 = *(const float4*)&Bs[cur][kt][tn * 4];
            const float av[8] = {a0.x, a0.y, a0.z, a0.w, a1.x, a1.y, a1.z, a1.w};
            const float bw[4] = {b4.x, b4.y, b4.z, b4.w};
            #pragma unroll
            for (int i = 0; i < 8; ++i)
                #pragma unroll
                for (int j = 0; j < 4; ++j)
                    acc[i][j] += av[i] * bw[j];
        }
        if (t + 1 < nTiles) {
            sts_tile(1 - cur);
            __syncthreads();
        }
    }

    #pragma unroll
    for (int i = 0; i < 8; ++i) {
        const int row = m0 + tm * 8 + i;
        float vmul = 1.f;
        if (epi == 2 && invf)
            vmul = (invf[z + (size_t)row * invRowStride] > 0.5f) ? 0.f : 1.f;
        #pragma unroll
        for (int j = 0; j < 4; ++j) {
            const int col = n0 + tn * 4 + j;
            if (col < N) {
                float v = acc[i][j];
                if (epi != 3 && bz) v += bz[col];
                if (epi == 1) v = fmaxf(v, 0.f);
                if (epi == 2) v *= vmul;
                C[(size_t)row * ldc + col] = v;
            }
        }
    }
}

// ==================== splitK reduce ====================
__global__ void reduce_kernel(const float* __restrict__ P, int nsplit, int total,
                              int ncol, const float* __restrict__ bias, int relu,
                              float* __restrict__ out)
{
    const int i = blockIdx.x * 256 + threadIdx.x;
    if (i < total) {
        float s = bias[i % ncol];
        for (int z = 0; z < nsplit; ++z) s += P[(size_t)z * total + i];
        if (relu) s = fmaxf(s, 0.f);
        out[i] = s;
    }
}

// ==================== attention: 4-way split, cp.async 2-group pipelined load ====
#define AK_LD  444                  // row stride floats = 111 float4 (16B aligned)
#define NSEG_F 43
#define NSEG_T 25
#define HB_A   (8 * NSEG_F)         // 344 f4 per 8-row batch
#define HB_TOT (8 * (2 * NSEG_F + NSEG_T))   // 888 f4 per 8-row batch

__global__ __launch_bounds__(128, 7)
void attn_q_kernel(const float* __restrict__ neigh_feat,
                   const float* __restrict__ neigh_time,
                   const float* __restrict__ edge_feat,
                   const void* __restrict__ mask_raw)
{
    __shared__ float kin[QRT * AK_LD];     // 28416 B
    __shared__ float ssm[2][QRT];
    __shared__ float ws[2][QRT];
    __shared__ float msk[QRT];

    const int b = blockIdx.x, r = blockIdx.y, qrt = blockIdx.z;
    const int idx = b * Rr + r;
    const int n0 = qrt * QRT;
    const int tid = threadIdx.x;
    const int lane = tid & 31, warp = tid >> 5;
    const float4 zero4 = make_float4(0.f, 0.f, 0.f, 0.f);
    const float scale = rsqrtf((float)Dhh);

    auto prefetch8 = [&](int batch) {
        const int nb = n0 + batch * 8;
        const float4* pa = (const float4*)(neigh_feat + ((size_t)idx * Nn + nb) * Ff);
        const float4* pb = (const float4*)(edge_feat  + ((size_t)idx * Nn + nb) * Ff);
        const float4* pc = (const float4*)(neigh_time + ((size_t)idx * Nn + nb) * Tt);
        #pragma unroll
        for (int it = 0; it < 7; ++it) {
            const int t = tid + it * 128;
            if (t < HB_TOT) {
                const float4* src;
                int row, col;
                if (t < HB_A) {
                    row = t / NSEG_F; const int s = t - row * NSEG_F;
                    col = s * 4; src = &pa[row * NSEG_F + s];
                } else if (t < 2 * HB_A) {
                    const int t2 = t - HB_A;
                    row = t2 / NSEG_F; const int s = t2 - row * NSEG_F;
                    col = Ff + s * 4; src = &pb[row * NSEG_F + s];
                } else {
                    const int t2 = t - 2 * HB_A;
                    row = t2 / NSEG_T; const int s = t2 - row * NSEG_T;
                    col = 2 * Ff + s * 4; src = &pc[row * NSEG_T + s];
                }
                cp_async16(&kin[(batch * 8 + row) * AK_LD + col], src);
            }
        }
        cp_commit();
    };

    prefetch8(0);
    prefetch8(1);

    if (tid < QRT) {
        const int mi = (r * Bn + b) * Nn + n0 + tid;
        int mv;
        if (g_mask_u8) mv = ((const unsigned char*)mask_raw)[mi];
        else           mv = ((const int*)mask_raw)[mi];
        msk[tid] = (mv != 0) ? 1.f : 0.f;
    }
    float4 q0[4], q1[4];
    {
        const float4* qkg4 = (const float4*)&g_qk[(size_t)idx * (2 * Kk)];
        #pragma unroll
        for (int k = 0; k < 4; ++k) {
            const int c = lane + 32 * k;
            const bool ok = (c < 111);
            q0[k] = ok ? qkg4[c]       : zero4;
            q1[k] = ok ? qkg4[111 + c] : zero4;
        }
    }

    auto score8 = [&](int batch) {
        #pragma unroll
        for (int i = 0; i < 2; ++i) {
            const int nl = batch * 8 + warp * 2 + i;
            const float4* krow = (const float4*)&kin[nl * AK_LD];
            float a0 = 0.f, a1 = 0.f;
            #pragma unroll
            for (int k = 0; k < 3; ++k) {
                const float4 v = krow[lane + 32 * k];
                a0 += dot4(v, q0[k]);
                a1 += dot4(v, q1[k]);
            }
            if (lane < 15) {
                const float4 v = krow[lane + 96];
                a0 += dot4(v, q0[3]);
                a1 += dot4(v, q1[3]);
            }
            a0 = warp_reduce(a0);
            a1 = warp_reduce(a1);
            if (lane == 0) {
                const bool pad = msk[nl] > 0.5f;
                ssm[0][nl] = pad ? -1e30f : a0 * scale;
                ssm[1][nl] = pad ? -1e30f : a1 * scale;
            }
        }
    };

    cp_wait<1>();
    __syncthreads();
    score8(0);
    cp_wait<0>();
    __syncthreads();
    score8(1);
    __syncthreads();

    if (warp == 0) {
        const int h = lane >> 4, p = lane & 15;
        float s = ssm[h][p];
        float m = s;
        #pragma unroll
        for (int o = 8; o; o >>= 1) m = fmaxf(m, __shfl_xor_sync(0xffffffffu, m, o));
        const float e = (msk[p] > 0.5f) ? 0.f : __expf(s - m);
        float l = e;
        #pragma unroll
        for (int o = 8; o; o >>= 1) l += __shfl_xor_sync(0xffffffffu, l, o);
        ws[h][p] = e;
        g_pw[((size_t)idx * 4 + qrt) * 32 + h * 16 + p] = e;
        if (p == 0) {
            g_pml[((size_t)idx * 4 + qrt) * 4 + h * 2 + 0] = m;
            g_pml[((size_t)idx * 4 + qrt) * 4 + h * 2 + 1] = l;
        }
    }
    __syncthreads();

    if (tid < 111) {
        float* pout = &g_pctx[((size_t)idx * 4 + qrt) * (2 * Kk)];
        float4 acc0 = zero4, acc1 = zero4;
        #pragma unroll
        for (int n = 0; n < QRT; ++n) {
            const float4 v = *(const float4*)&kin[n * AK_LD + 4 * tid];
            const float w0 = ws[0][n], w1 = ws[1][n];
            acc0.x += w0 * v.x; acc0.y += w0 * v.y;
            acc0.z += w0 * v.z; acc0.w += w0 * v.w;
            acc1.x += w1 * v.x; acc1.y += w1 * v.y;
            acc1.z += w1 * v.z; acc1.w += w1 * v.w;
        }
        *(float4*)&pout[4 * tid]      = acc0;
        *(float4*)&pout[Kk + 4 * tid] = acc1;
    }
}

// ==================== merge 4 quarters (float4) ====================
__global__ __launch_bounds__(128)
void merge4_kernel(float* __restrict__ wavg_out)
{
    const int idx = blockIdx.x;
    const int tid = threadIdx.x;
    __shared__ float fs[4][2];
    __shared__ int inval;

    if (tid == 0) {
        bool bad = false;
        #pragma unroll
        for (int h = 0; h < 2; ++h) {
            float m[4], l[4];
            float M = -1e38f;
            #pragma unroll
            for (int s = 0; s < 4; ++s) {
                m[s] = g_pml[((size_t)idx * 4 + s) * 4 + h * 2 + 0];
                l[s] = g_pml[((size_t)idx * 4 + s) * 4 + h * 2 + 1];
                M = fmaxf(M, m[s]);
            }
            float L = 0.f, e[4];
            #pragma unroll
            for (int s = 0; s < 4; ++s) { e[s] = __expf(m[s] - M); L += l[s] * e[s]; }
            if (L <= 0.f) { bad = true; fs[0][h] = fs[1][h] = fs[2][h] = fs[3][h] = 0.f; }
            else {
                const float inv = 1.f / L;
                #pragma unroll
                for (int s = 0; s < 4; ++s) fs[s][h] = e[s] * inv;
            }
        }
        inval = bad ? 1 : 0;
        g_inv[idx] = bad ? 1.f : 0.f;
    }
    __syncthreads();

    float4* out = (float4*)&g_ctx[(size_t)idx * (2 * Kk)];   // 222 float4
    const float4 zero4 = make_float4(0.f, 0.f, 0.f, 0.f);
    if (inval) {
        for (int t = tid; t < 222; t += 128) out[t] = zero4;
        if (wavg_out && tid < Nn) wavg_out[idx * Nn + tid] = 0.f;
        return;
    }
    for (int t = tid; t < 222; t += 128) {
        const int h = (t >= 111) ? 1 : 0;
        float4 v = zero4;
        #pragma unroll
        for (int s = 0; s < 4; ++s) {
            const float4 p = ((const float4*)&g_pctx[((size_t)idx * 4 + s) * (2 * Kk)])[t];
            const float f = fs[s][h];
            v.x += f * p.x; v.y += f * p.y; v.z += f * p.z; v.w += f * p.w;
        }
        out[t] = v;
    }
    if (wavg_out && tid < Nn) {
        const int s = tid >> 4, p = tid & 15;
        const float w0 = g_pw[((size_t)idx * 4 + s) * 32 + p]      * fs[s][0];
        const float w1 = g_pw[((size_t)idx * 4 + s) * 32 + 16 + p] * fs[s][1];
        wavg_out[idx * Nn + tid] = 0.5f * (w0 + w1);
    }
}

// ==================== launch ====================
extern "C" void kernel_launch(void* const* d_in, const int* in_sizes, int n_in,
                              void* d_out, int out_size)
{
    const float* src_node = (const float*)d_in[0];
    const float* src_time = (const float*)d_in[1];
    const float* nf       = (const float*)d_in[2];
    const float* nt       = (const float*)d_in[3];
    const float* ef       = (const float*)d_in[4];
    const void*  mask     = d_in[5];
    const float* Wq = (const float*)d_in[6];
    const float* Wk = (const float*)d_in[7];
    const float* Wv = (const float*)d_in[8];
    const float* bq = (const float*)d_in[9];
    // bk dropped: softmax-invariant
    const float* bv = (const float*)d_in[11];
    const float* Wo = (const float*)d_in[12];
    const float* bo = (const float*)d_in[13];
    const float* W1 = (const float*)d_in[14];
    const float* b1 = (const float*)d_in[15];
    const float* W2 = (const float*)d_in[16];
    const float* b2 = (const float*)d_in[17];

    float* merged = (float*)d_out;
    float* wavg = nullptr;
    if (out_size >= Bn * OUTF + Bn * Rr * Nn)
        wavg = merged + Bn * OUTF;

    float *pX, *pq, *pqk, *pctx, *pattn, *pcat, *ph1, *pinv, *pf1, *pf2;
    cudaGetSymbolAddress((void**)&pX,    g_X);
    cudaGetSymbolAddress((void**)&pq,    g_q);
    cudaGetSymbolAddress((void**)&pqk,   g_qk);
    cudaGetSymbolAddress((void**)&pctx,  g_ctx);
    cudaGetSymbolAddress((void**)&pattn, g_attn);
    cudaGetSymbolAddress((void**)&pcat,  g_cat);
    cudaGetSymbolAddress((void**)&ph1,   g_h1);
    cudaGetSymbolAddress((void**)&pinv,  g_inv);
    cudaGetSymbolAddress((void**)&pf1,   g_f1p);
    cudaGetSymbolAddress((void**)&pf2,   g_f2p);

    // prep + mask-dtype detect (extra block)
    prep_X_kernel<<<Bn + 1, 256>>>(src_node, src_time, (const unsigned int*)mask);

    // q = X @ Wq[r]^T + bq   (NT, z=r)
    {
        dim3 g(Bn / 64, (Ee + 63) / 64, Rr);
        gemm2_kernel<true><<<g, 128>>>(pX, Ee, 0,
                                       Wq, Ee, (long)Ee * Ee,
                                       pq, Rr * Ee, Ee,
                                       bq, Ee, nullptr, 0,
                                       Ee, Ee, 0, 0);
    }
    // qk = q_h @ Wk_h   (NN, z=2r+h)
    {
        dim3 g(Bn / 64, (Kk + 63) / 64, Rr * 2);
        gemm2_kernel<false><<<g, 128>>>(pq, Rr * Ee, Dhh,
                                        Wk, Kk, (long)Dhh * Kk,
                                        pqk, Rr * 2 * Kk, Kk,
                                        nullptr, 0, nullptr, 0,
                                        Kk, Dhh, 0, 0);
    }
    // attention: 4-way split (pipelined load) + merge
    {
        dim3 g(Bn, Rr, 4);
        attn_q_kernel<<<g, 128>>>(nf, nt, ef, mask);
        merge4_kernel<<<Bn * Rr, 128>>>(wavg);
    }
    // attn = ctx @ Wv_h^T + bv   (NT, z=2r+h)
    {
        dim3 g(Bn / 64, (Dhh + 63) / 64, Rr * 2);
        gemm2_kernel<true><<<g, 128>>>(pctx, Rr * 2 * Kk, Kk,
                                       Wv, Kk, (long)Dhh * Kk,
                                       pattn, Rr * Ee, Dhh,
                                       bv, Dhh, nullptr, 0,
                                       Dhh, Kk, 0, 0);
    }
    // out = attn @ Wo[r]^T + bo, zero where invalid -> g_cat  (NT, epi 2)
    {
        dim3 g(Bn / 64, (Ee + 63) / 64, Rr);
        gemm2_kernel<true><<<g, 128>>>(pattn, Rr * Ee, Ee,
                                       Wo, Ee, (long)Ee * Ee,
                                       pcat, CATN, Ee,
                                       bo, Ee,
                                       pinv, Rr,
                                       Ee, Ee, 2, 0);
    }
    // fc1: splitK-12 partials, then reduce(+bias,+relu)
    {
        dim3 g(Bn / 64, (OUTF + 63) / 64, F1SPLIT);
        gemm2_kernel<true><<<g, 128>>>(pcat, CATN, 0,
                                       W1, CATN, 0,
                                       pf1, OUTF, (long)Bn * OUTF,
                                       nullptr, 0, nullptr, 0,
                                       OUTF, CATN, 3, F1CHUNK);
        reduce_kernel<<<(Bn * OUTF + 255) / 256, 256>>>(pf1, F1SPLIT, Bn * OUTF, OUTF, b1, 1, ph1);
    }
    // fc2: splitK-4 partials, then reduce(+bias)
    {
        dim3 g(Bn / 64, (OUTF + 63) / 64, F2SPLIT);
        gemm2_kernel<true><<<g, 128>>>(ph1, OUTF, 0,
                                       W2, OUTF, 0,
                                       pf2, OUTF, (long)Bn * OUTF,
                                       nullptr, 0, nullptr, 0,
                                       OUTF, OUTF, 3, F2CHUNK);
        reduce_kernel<<<(Bn * OUTF + 255) / 256, 256>>>(pf2, F2SPLIT, Bn * OUTF, OUTF, b2, 0, merged);
    }
}